// round 15
// baseline (speedup 1.0000x reference)
#include <cuda_runtime.h>
#include <cuda_fp16.h>
#include <cstdint>
#include <math.h>

#define E_TOT 262144
#define NN    16384
#define H     256
#define NG    64

// ---------------- scratch ----------------
__device__ __half g_hidden[(size_t)E_TOT * H];  // hidden_t, fp16
__device__ __half g_pre[(size_t)E_TOT * H];     // hidden pre-activation, fp16
__device__ float g_s[NN];
__device__ float g_bv[(size_t)NN * H];
__device__ float g_agg[(size_t)NN * H];
__device__ float g_U[(size_t)NN * H];
__device__ float g_V[(size_t)NN * H];
__device__ float g_gG[NG * 768];
__device__ float g_z[NG];

// composed fp32 vectors
__device__ float g_cbsc[H];
__device__ float g_cbth[H];
__device__ float g_cU[H];
__device__ float g_cV[H];
__device__ float g_wcomp[H];
__device__ float g_cconst[1];
__device__ float g_inv[NN], g_rs[NN], g_ish[NN], g_ist[NN];

// fp16 weights, K-major B[n][k]
__device__ __half g_h_sc0[H*H];
__device__ __half g_h_sc[H*H];
__device__ __half g_h_th0[H*H];
__device__ __half g_h_th[H*H];
__device__ __half g_h_u[H*H];
__device__ __half g_h_v[H*H];
__device__ __half g_h_u2[H*H];
__device__ __half g_h_v2[H*H];
__device__ __half g_h_w2[H*H];

// ---------------- prep kernels ----------------

struct CompJobs { const float* R[4]; __half* dst[4]; };
__global__ void comp_mat_h(const float* __restrict__ L, CompJobs jobs) {
    __shared__ float lrow[H];
    int m = blockIdx.y, k = blockIdx.x, n = threadIdx.x;
    lrow[n] = L[k * H + n];
    __syncthreads();
    const float* R = jobs.R[m];
    float acc = 0.f;
    for (int j = 0; j < H; j++) acc = fmaf(lrow[j], R[j * H + n], acc);
    jobs.dst[m][(size_t)n * H + k] = __float2half_rn(acc);
}

struct ConvJobs { const float* src[5]; __half* dst[5]; };
__global__ void conv_w_batch(ConvJobs jobs) {
    int m = blockIdx.y;
    int idx = blockIdx.x * 256 + threadIdx.x;
    int n = idx >> 8, k = idx & 255;
    jobs.dst[m][(size_t)n * H + k] = __float2half_rn(jobs.src[m][(size_t)k * H + n]);
}

__global__ void comp_vec(const float* __restrict__ eu_w2, const float* __restrict__ eu_b2,
                         const float* __restrict__ ea_w1, const float* __restrict__ ea_b1,
                         const float* __restrict__ w1c, const float* __restrict__ eu_b1,
                         const float* __restrict__ w1a, const float* __restrict__ w1b,
                         const float* __restrict__ ew_w, const float* __restrict__ ew_b) {
    __shared__ float ra[H], rb[H], rw[H], rc[H], ru[H], rv[H];
    int n = blockIdx.x, k = threadIdx.x;
    float e2 = eu_b2[k];
    ra[k] = e2 * ea_w1[k * H + n];
    rb[k] = e2 * w1c[k * H + n];
    ru[k] = e2 * w1a[k * H + n];
    rv[k] = e2 * w1b[k * H + n];
    rw[k] = eu_w2[n * H + k] * ew_w[k];
    rc[k] = e2 * ew_w[k];
    __syncthreads();
    for (int s = 128; s > 0; s >>= 1) {
        if (k < s) {
            ra[k] += ra[k+s]; rb[k] += rb[k+s]; rw[k] += rw[k+s];
            rc[k] += rc[k+s]; ru[k] += ru[k+s]; rv[k] += rv[k+s];
        }
        __syncthreads();
    }
    if (k == 0) {
        g_cbsc[n] = ra[0] + ea_b1[n];
        g_cbth[n] = rb[0] + eu_b1[n];
        g_cU[n] = ru[0];
        g_cV[n] = rv[0];
        g_wcomp[n] = rw[0];
        if (n == 0) g_cconst[0] = rc[0] + ew_b[0];
    }
}

__global__ void deg_kernel(const int* __restrict__ deg, const int* __restrict__ batch,
                           const int* __restrict__ heads, const int* __restrict__ tails) {
    int n = blockIdx.x * 256 + threadIdx.x;
    int d = deg[n];
    float inv = 1.f / (1.f + (float)d);
    g_inv[n] = inv;
    g_rs[n] = (d > 0) ? inv : 0.f;
    int b = batch[n];
    g_ish[n] = (heads[b] == n) ? 1.f : 0.f;
    g_ist[n] = (tails[b] == n) ? 1.f : 0.f;
}

__global__ void init_iter_kernel(float* __restrict__ dst) {
    int t = blockIdx.x * 256 + threadIdx.x;
    if (t < NN * H) dst[t] = 0.f;
    if (t < NN) g_s[t] = 0.f;
}

// ---------------- common helpers ----------------

#define MMA_F16(d, a, b0, b1)                                               \
    asm volatile("mma.sync.aligned.m16n8k16.row.col.f32.f16.f16.f32 "       \
        "{%0,%1,%2,%3}, {%4,%5,%6,%7}, {%8,%9}, {%0,%1,%2,%3};"             \
        : "+f"((d)[0]), "+f"((d)[1]), "+f"((d)[2]), "+f"((d)[3])            \
        : "r"((a)[0]), "r"((a)[1]), "r"((a)[2]), "r"((a)[3]),               \
          "r"(b0), "r"(b1))

#define LDSM_X4(r, addr)                                                    \
    asm volatile("ldmatrix.sync.aligned.m8n8.x4.shared.b16 {%0,%1,%2,%3}, [%4];" \
        : "=r"((r)[0]), "=r"((r)[1]), "=r"((r)[2]), "=r"((r)[3]) : "r"(addr))

__device__ __forceinline__ uint32_t pack_h2(float x, float y) {
    __half2 h = __floats2half2_rn(x, y);
    return *(uint32_t*)&h;
}

__device__ __forceinline__ uint32_t smem_u32(const void* p) {
    return (uint32_t)__cvta_generic_to_shared(p);
}

// ---------------- fused edge GEMM: score(+softmax+scatter) | hidden-pre ----------------
// grid = 8192: blocks [0,4096) -> score, [4096,8192) -> pre
// A: FIRST=1 -> [ef | gall]; FIRST=0 -> g_hidden fp16
// Double-buffered B smem: stage tile t+1 while MMA consumes tile t; 1 sync/tile.

#define AFSTRIDE 264
#define S_OFF_A    0                    // 64*264*2 = 33792
#define S_OFF_B    33792                // 2 x 256*40*2 = 40960
#define BBUF_BYTES 20480
#define S_OFF_SB1  74752
#define S_OFF_SWV  75776
#define S_OFF_RSUM 76800
#define S_OFF_SEX  77056
#define S_OFF_RCV  77312
#define S_SMEM     77568
#define BSTRIDE 40
#define ASTRIDE 40

template<int FIRST>
__global__ __launch_bounds__(256, 2) void edge_gemm(
    const float* __restrict__ ef, const float* __restrict__ gall,
    const __half* __restrict__ Ahid,
    const __half* __restrict__ Bsc, const __half* __restrict__ Bth,
    const float* __restrict__ bsc, const float* __restrict__ bth,
    const float* __restrict__ wvp, const float* __restrict__ wbp,
    const int* __restrict__ recvp, float* __restrict__ aggdst)
{
    extern __shared__ char smem[];
    __half* Af = (__half*)(smem + S_OFF_A);
    __half* Bh = (__half*)(smem + S_OFF_B);
    float* sb1  = (float*)(smem + S_OFF_SB1);
    float* swv  = (float*)(smem + S_OFF_SWV);
    float* rsum = (float*)(smem + S_OFF_RSUM);
    float* sex  = (float*)(smem + S_OFF_SEX);
    int*   srcv = (int*)(smem + S_OFF_RCV);

    const int tid = threadIdx.x, lane = tid & 31, wid = tid >> 5;
    const int half = blockIdx.x >> 12;          // 0 = score, 1 = pre
    const int row0 = (blockIdx.x & 4095) * 64;
    const int mbase = (wid >> 2) * 32, nbase = (wid & 3) * 64;
    const __half* Bg = half ? Bth : Bsc;

    sb1[tid] = half ? bth[tid] : bsc[tid];
    if (!half) {
        swv[tid] = wvp[tid];
        if (tid < 64) { rsum[tid] = 0.f; srcv[tid] = recvp[row0 + tid]; }
    }

    // ---- build/load A tile (64 x 256 halves) ----
    {
        int r = tid >> 2, c0 = (tid & 3) * 64;
        if (FIRST) {
            #pragma unroll
            for (int j = 0; j < 8; j++) {
                int c = c0 + j * 8;
                const float* sp = (c < 192) ? (ef + (size_t)(row0 + r) * 192 + c)
                                            : (gall + (c - 192));
                float4 a = *(const float4*)sp;
                float4 b = *(const float4*)(sp + 4);
                uint4 u;
                u.x = pack_h2(a.x, a.y); u.y = pack_h2(a.z, a.w);
                u.z = pack_h2(b.x, b.y); u.w = pack_h2(b.z, b.w);
                *(uint4*)&Af[r * AFSTRIDE + c] = u;
            }
        } else {
            #pragma unroll
            for (int j = 0; j < 8; j++) {
                uint4 u = *(const uint4*)(Ahid + (size_t)(row0 + r) * H + c0 + j * 8);
                *(uint4*)&Af[r * AFSTRIDE + c0 + j * 8] = u;
            }
        }
    }

    float acc[2][8][4];
    #pragma unroll
    for (int mf = 0; mf < 2; mf++)
        #pragma unroll
        for (int nf = 0; nf < 8; nf++)
            #pragma unroll
            for (int q = 0; q < 4; q++) acc[mf][nf][q] = 0.f;

    // per-lane LDSM base addresses
    const uint32_t a_base = smem_u32(Af)
        + (uint32_t)(((mbase + (lane & 15)) * AFSTRIDE + ((lane >> 4) * 8)) * 2);
    const uint32_t b_base0 = smem_u32(Bh)
        + (uint32_t)((((nbase + ((lane >> 4) * 8) + (lane & 7)) * BSTRIDE)
                      + (((lane >> 3) & 1) * 8)) * 2);

    // ---- stage B tile 0 into buffer 0 ----
    const __half* bptr = Bg + (size_t)tid * H;
    {
        #pragma unroll
        for (int j = 0; j < 4; j++)
            *(uint4*)&Bh[tid * BSTRIDE + j * 8] = *(const uint4*)(bptr + j * 8);
    }
    __syncthreads();

    for (int kt = 0; kt < H; kt += 32) {
        const int cur = (kt >> 5) & 1;
        // stage next tile into the other buffer (overlaps with MMA below)
        if (kt + 32 < H) {
            __half* bdst = Bh + (cur ^ 1) * (BBUF_BYTES / 2);
            #pragma unroll
            for (int j = 0; j < 4; j++)
                *(uint4*)&bdst[tid * BSTRIDE + j * 8] = *(const uint4*)(bptr + kt + 32 + j * 8);
        }
        const uint32_t b_base = b_base0 + (uint32_t)(cur * BBUF_BYTES);
        #pragma unroll
        for (int ks = 0; ks < 2; ks++) {
            uint32_t af0[4], af1[4];
            LDSM_X4(af0, a_base + (uint32_t)((kt + ks * 16) * 2));
            LDSM_X4(af1, a_base + (uint32_t)((kt + ks * 16) * 2 + 16 * AFSTRIDE * 2));
            #pragma unroll
            for (int p = 0; p < 4; p++) {
                uint32_t bb[4];
                LDSM_X4(bb, b_base + (uint32_t)((p * 16 * BSTRIDE + ks * 16) * 2));
                MMA_F16(acc[0][2 * p],     af0, bb[0], bb[1]);
                MMA_F16(acc[1][2 * p],     af1, bb[0], bb[1]);
                MMA_F16(acc[0][2 * p + 1], af0, bb[2], bb[3]);
                MMA_F16(acc[1][2 * p + 1], af1, bb[2], bb[3]);
            }
        }
        __syncthreads();
    }

    if (half) {
        #pragma unroll
        for (int mf = 0; mf < 2; mf++)
            #pragma unroll
            for (int nf = 0; nf < 8; nf++) {
                int rA = mbase + mf * 16 + (lane >> 2);
                int rB = rA + 8;
                int c0 = nbase + nf * 8 + (lane & 3) * 2;
                float bb0 = sb1[c0], bb1 = sb1[c0 + 1];
                *(uint32_t*)(g_pre + (size_t)(row0 + rA) * H + c0) =
                    pack_h2(acc[mf][nf][0] + bb0, acc[mf][nf][1] + bb1);
                *(uint32_t*)(g_pre + (size_t)(row0 + rB) * H + c0) =
                    pack_h2(acc[mf][nf][2] + bb0, acc[mf][nf][3] + bb1);
            }
    } else {
        float part[2][2] = {{0.f, 0.f}, {0.f, 0.f}};
        #pragma unroll
        for (int mf = 0; mf < 2; mf++)
            #pragma unroll
            for (int nf = 0; nf < 8; nf++) {
                int c0 = nbase + nf * 8 + (lane & 3) * 2;
                float w0 = swv[c0], w1 = swv[c0 + 1];
                float bb0 = sb1[c0], bb1 = sb1[c0 + 1];
                float v0 = fmaxf(acc[mf][nf][0] + bb0, 0.f);
                float v1 = fmaxf(acc[mf][nf][1] + bb1, 0.f);
                float v2 = fmaxf(acc[mf][nf][2] + bb0, 0.f);
                float v3 = fmaxf(acc[mf][nf][3] + bb1, 0.f);
                part[mf][0] = fmaf(v0, w0, fmaf(v1, w1, part[mf][0]));
                part[mf][1] = fmaf(v2, w0, fmaf(v3, w1, part[mf][1]));
            }
        #pragma unroll
        for (int off = 1; off <= 2; off <<= 1)
            #pragma unroll
            for (int mf = 0; mf < 2; mf++) {
                part[mf][0] += __shfl_xor_sync(0xffffffffu, part[mf][0], off);
                part[mf][1] += __shfl_xor_sync(0xffffffffu, part[mf][1], off);
            }
        if ((lane & 3) == 0) {
            #pragma unroll
            for (int mf = 0; mf < 2; mf++) {
                atomicAdd(&rsum[mbase + mf * 16 + (lane >> 2)],     part[mf][0]);
                atomicAdd(&rsum[mbase + mf * 16 + (lane >> 2) + 8], part[mf][1]);
            }
        }
        __syncthreads();
        if (tid < 64) {
            float sg = 1.f / (1.f + expf(-(rsum[tid] + wbp[0])));
            float ex = expf(sg);
            sex[tid] = ex;
            atomicAdd(&g_s[srcv[tid]], ex);
        }
        __syncthreads();
        int r = tid >> 2, c0 = (tid & 3) * 64;
        float exv = sex[r];
        float* drow = aggdst + (size_t)srcv[r] * H + c0;
        const __half* arow = Af + r * AFSTRIDE + c0;
        #pragma unroll
        for (int j = 0; j < 16; j++) {
            float2 f0 = __half22float2(*(const __half2*)(arow + j * 4));
            float2 f1 = __half22float2(*(const __half2*)(arow + j * 4 + 2));
            asm volatile("red.global.add.v4.f32 [%0], {%1, %2, %3, %4};"
                         :: "l"(drow + j * 4), "f"(exv * f0.x), "f"(exv * f0.y),
                            "f"(exv * f1.x), "f"(exv * f1.y) : "memory");
        }
    }
}

// ---------------- node GEMM: roles U | V | bv from row-scaled agg ----------------

#define N_OFF_AH 0
#define N_OFF_BH 5120
#define N_OFF_CV 25600
#define N_OFF_FH 26624
#define N_OFF_FT 27648
#define N_OFF_R1 28672
#define N_OFF_R2 28928
#define N_OFF_I1 29184
#define N_OFF_I2 29440
#define N_SMEM   29696

__global__ __launch_bounds__(256) void node_gemm(
    const __half* __restrict__ Bu, const __half* __restrict__ Bv,
    const __half* __restrict__ Bw2,
    const float* __restrict__ cU, const float* __restrict__ cV,
    const float* __restrict__ cBv,
    const float* __restrict__ fhU, const float* __restrict__ ftU,
    const float* __restrict__ fhV, const float* __restrict__ ftV)
{
    extern __shared__ char smem[];
    __half* Ah = (__half*)(smem + N_OFF_AH);
    __half* Bh = (__half*)(smem + N_OFF_BH);
    float* scv = (float*)(smem + N_OFF_CV);
    float* sfh = (float*)(smem + N_OFF_FH);
    float* sft = (float*)(smem + N_OFF_FT);
    float* s_r1 = (float*)(smem + N_OFF_R1);
    float* s_r2 = (float*)(smem + N_OFF_R2);
    float* s_i1 = (float*)(smem + N_OFF_I1);
    float* s_i2 = (float*)(smem + N_OFF_I2);

    const int tid = threadIdx.x, lane = tid & 31, wid = tid >> 5;
    const int role = blockIdx.x >> 8;
    const int row0 = (blockIdx.x & 255) * 64;
    const int mbase = (wid >> 2) * 32, nbase = (wid & 3) * 64;

    const __half* Bg = (role == 0) ? Bu : (role == 1) ? Bv : Bw2;
    const float* cvec = (role == 0) ? cU : (role == 1) ? cV : cBv;
    const float* fh = (role == 0) ? fhU : (role == 1) ? fhV : nullptr;
    const float* ft = (role == 0) ? ftU : (role == 1) ? ftV : nullptr;
    float* outp = (role == 0) ? g_U : (role == 1) ? g_V : g_bv;

    scv[tid] = cvec ? cvec[tid] : 0.f;
    sfh[tid] = fh ? fh[tid] : 0.f;
    sft[tid] = ft ? ft[tid] : 0.f;
    if (tid < 64) {
        int n = row0 + tid;
        float s = g_s[n];
        s_r1[tid] = (s > 0.f) ? g_inv[n] / s : 0.f;
        s_r2[tid] = g_rs[n];
        s_i1[tid] = g_ish[n];
        s_i2[tid] = g_ist[n];
    }
    __syncthreads();

    float acc[2][8][4];
    #pragma unroll
    for (int mf = 0; mf < 2; mf++)
        #pragma unroll
        for (int nf = 0; nf < 8; nf++)
            #pragma unroll
            for (int q = 0; q < 4; q++) acc[mf][nf][q] = 0.f;

    const int arow = tid >> 2, ac0 = (tid & 3) * 8;

    for (int kt = 0; kt < H; kt += 32) {
        {
            float x[8];
            *(float4*)&x[0] = *(const float4*)(g_agg + (size_t)(row0 + arow) * H + kt + ac0);
            *(float4*)&x[4] = *(const float4*)(g_agg + (size_t)(row0 + arow) * H + kt + ac0 + 4);
            float sc = s_r1[arow];
            uint4 u;
            u.x = pack_h2(x[0] * sc, x[1] * sc);
            u.y = pack_h2(x[2] * sc, x[3] * sc);
            u.z = pack_h2(x[4] * sc, x[5] * sc);
            u.w = pack_h2(x[6] * sc, x[7] * sc);
            *(uint4*)&Ah[arow * ASTRIDE + ac0] = u;
        }
        {
            const __half* bsrc = Bg + (size_t)tid * H + kt;
            #pragma unroll
            for (int j = 0; j < 4; j++)
                *(uint4*)&Bh[tid * BSTRIDE + j * 8] = *(const uint4*)(bsrc + j * 8);
        }
        __syncthreads();
        #pragma unroll
        for (int ks = 0; ks < 2; ks++) {
            const int k0 = ks * 16 + (lane & 3) * 2;
            uint32_t af[2][4];
            #pragma unroll
            for (int mf = 0; mf < 2; mf++) {
                int r = mbase + mf * 16 + (lane >> 2);
                af[mf][0] = *(uint32_t*)&Ah[r * ASTRIDE + k0];
                af[mf][1] = *(uint32_t*)&Ah[(r + 8) * ASTRIDE + k0];
                af[mf][2] = *(uint32_t*)&Ah[r * ASTRIDE + k0 + 8];
                af[mf][3] = *(uint32_t*)&Ah[(r + 8) * ASTRIDE + k0 + 8];
            }
            #pragma unroll
            for (int nf = 0; nf < 8; nf++) {
                int n = nbase + nf * 8 + (lane >> 2);
                uint32_t b0 = *(uint32_t*)&Bh[n * BSTRIDE + k0];
                uint32_t b1 = *(uint32_t*)&Bh[n * BSTRIDE + k0 + 8];
                #pragma unroll
                for (int mf = 0; mf < 2; mf++)
                    MMA_F16(acc[mf][nf], af[mf], b0, b1);
            }
        }
        __syncthreads();
    }

    #pragma unroll
    for (int mf = 0; mf < 2; mf++)
        #pragma unroll
        for (int nf = 0; nf < 8; nf++) {
            int rA = mbase + mf * 16 + (lane >> 2);
            int rB = rA + 8;
            int c0 = nbase + nf * 8 + (lane & 3) * 2;
            float cv0 = scv[c0], cv1 = scv[c0 + 1];
            float fh0 = sfh[c0], fh1 = sfh[c0 + 1];
            float ft0 = sft[c0], ft1 = sft[c0 + 1];
            float2 v0, v1;
            v0.x = acc[mf][nf][0] + s_r2[rA] * cv0 + s_i1[rA] * fh0 + s_i2[rA] * ft0;
            v0.y = acc[mf][nf][1] + s_r2[rA] * cv1 + s_i1[rA] * fh1 + s_i2[rA] * ft1;
            v1.x = acc[mf][nf][2] + s_r2[rB] * cv0 + s_i1[rB] * fh0 + s_i2[rB] * ft0;
            v1.y = acc[mf][nf][3] + s_r2[rB] * cv1 + s_i1[rB] * fh1 + s_i2[rB] * ft1;
            *(float2*)(outp + (size_t)(row0 + rA) * H + c0) = v0;
            *(float2*)(outp + (size_t)(row0 + rB) * H + c0) = v1;
        }
}

// ---------------- finalize: hidden = relu(pre + U[src] + V[recv]) ----------------

__global__ void finalize_hidden(const int* __restrict__ srcp, const int* __restrict__ recvp) {
    int t = blockIdx.x * 256 + threadIdx.x;
    int e = t >> 5, j = (t & 31) * 8;
    int s = srcp[e], r = recvp[e];
    uint4 ph = *(const uint4*)(g_pre + (size_t)e * H + j);
    float4 u0 = *(const float4*)(g_U + (size_t)s * H + j);
    float4 u1 = *(const float4*)(g_U + (size_t)s * H + j + 4);
    float4 v0 = *(const float4*)(g_V + (size_t)r * H + j);
    float4 v1 = *(const float4*)(g_V + (size_t)r * H + j + 4);
    float2 p0 = __half22float2(*(__half2*)&ph.x);
    float2 p1 = __half22float2(*(__half2*)&ph.y);
    float2 p2 = __half22float2(*(__half2*)&ph.z);
    float2 p3 = __half22float2(*(__half2*)&ph.w);
    uint4 o;
    o.x = pack_h2(fmaxf(p0.x + u0.x + v0.x, 0.f), fmaxf(p0.y + u0.y + v0.y, 0.f));
    o.y = pack_h2(fmaxf(p1.x + u0.z + v0.z, 0.f), fmaxf(p1.y + u0.w + v0.w, 0.f));
    o.z = pack_h2(fmaxf(p2.x + u1.x + v1.x, 0.f), fmaxf(p2.y + u1.y + v1.y, 0.f));
    o.w = pack_h2(fmaxf(p3.x + u1.z + v1.z, 0.f), fmaxf(p3.y + u1.w + v1.w, 0.f));
    *(uint4*)(g_hidden + (size_t)e * H + j) = o;
}

__global__ void finalize_we(const int* __restrict__ srcp, const int* __restrict__ recvp,
                            float* __restrict__ out) {
    __shared__ float wc[H];
    int tid = threadIdx.x, lane = tid & 31, wid = tid >> 5;
    wc[tid] = g_wcomp[tid];
    __syncthreads();
    int e = blockIdx.x * 8 + wid;
    int s = srcp[e], r = recvp[e];
    int j = lane * 8;
    uint4 ph = *(const uint4*)(g_pre + (size_t)e * H + j);
    float4 u0 = *(const float4*)(g_U + (size_t)s * H + j);
    float4 u1 = *(const float4*)(g_U + (size_t)s * H + j + 4);
    float4 v0 = *(const float4*)(g_V + (size_t)r * H + j);
    float4 v1 = *(const float4*)(g_V + (size_t)r * H + j + 4);
    float2 p0 = __half22float2(*(__half2*)&ph.x);
    float2 p1 = __half22float2(*(__half2*)&ph.y);
    float2 p2 = __half22float2(*(__half2*)&ph.z);
    float2 p3 = __half22float2(*(__half2*)&ph.w);
    const float* w = wc + j;
    float acc = fmaxf(p0.x + u0.x + v0.x, 0.f) * w[0]
              + fmaxf(p0.y + u0.y + v0.y, 0.f) * w[1]
              + fmaxf(p1.x + u0.z + v0.z, 0.f) * w[2]
              + fmaxf(p1.y + u0.w + v0.w, 0.f) * w[3]
              + fmaxf(p2.x + u1.x + v1.x, 0.f) * w[4]
              + fmaxf(p2.y + u1.y + v1.y, 0.f) * w[5]
              + fmaxf(p3.x + u1.z + v1.z, 0.f) * w[6]
              + fmaxf(p3.y + u1.w + v1.w, 0.f) * w[7];
    #pragma unroll
    for (int off = 16; off > 0; off >>= 1) acc += __shfl_xor_sync(0xffffffffu, acc, off);
    if (lane == 0) out[e] = 1.f / (1.f + expf(-(acc + g_cconst[0])));
}

// ---------------- graph readout ----------------

__global__ void gmax_kernel(const int* __restrict__ heads, const int* __restrict__ tails) {
    int g = blockIdx.x, j = threadIdx.x;
    float mx = -3.4e38f;
    int base = g * 256;
    for (int n = 0; n < 256; n++)
        mx = fmaxf(mx, g_bv[(size_t)(base + n) * H + j]);
    g_gG[g * 768 + j]       = mx;
    g_gG[g * 768 + 256 + j] = g_bv[(size_t)heads[g] * H + j];
    g_gG[g * 768 + 512 + j] = g_bv[(size_t)tails[g] * H + j];
}

__global__ void gmlp_kernel(const float* __restrict__ W1, const float* __restrict__ b1,
                            const float* __restrict__ w2, const float* __restrict__ b2) {
    __shared__ float row[768];
    __shared__ float red[256];
    int g = blockIdx.x, tid = threadIdx.x;
    for (int i = tid; i < 768; i += 256) row[i] = g_gG[g * 768 + i];
    __syncthreads();
    float h = b1[tid];
    for (int k = 0; k < 768; k++) h = fmaf(row[k], W1[(size_t)k * 256 + tid], h);
    h = fmaxf(h, 0.f);
    red[tid] = h * w2[tid];
    __syncthreads();
    for (int s = 128; s > 0; s >>= 1) {
        if (tid < s) red[tid] += red[tid + s];
        __syncthreads();
    }
    if (tid == 0) g_z[g] = red[0] + b2[0];
}

__global__ void gout_kernel(float* __restrict__ out) {
    __shared__ float zs[NG];
    int tid = threadIdx.x;
    if (tid < NG) zs[tid] = g_z[tid];
    __syncthreads();
    float m = -3.4e38f;
    for (int g = 0; g < NG; g++) m = fmaxf(m, zs[g]);
    float denom = 0.f;
    for (int g = 0; g < NG; g++) denom += expf(zs[g] - m);
    float acc = 0.f;
    for (int g = 0; g < NG; g++) acc += (expf(zs[g] - m) / denom) * g_gG[g * 768 + tid];
    out[tid] = acc;
}

// ---------------- launch ----------------

static float* dev_ptr(const void* sym) { void* p = nullptr; cudaGetSymbolAddress(&p, sym); return (float*)p; }

extern "C" void kernel_launch(void* const* d_in, const int* in_sizes, int n_in,
                              void* d_out, int out_size) {
    const float* ef     = (const float*)d_in[0];
    const float* gall   = (const float*)d_in[1];
    const float* ea_w1  = (const float*)d_in[2];
    const float* ea_b1  = (const float*)d_in[3];
    const float* ea_w2  = (const float*)d_in[4];
    const float* ea_b2  = (const float*)d_in[5];
    const float* eu_w1  = (const float*)d_in[6];
    const float* eu_b1  = (const float*)d_in[7];
    const float* eu_w2  = (const float*)d_in[8];
    const float* eu_b2  = (const float*)d_in[9];
    const float* gw_w1  = (const float*)d_in[10];
    const float* gw_b1  = (const float*)d_in[11];
    const float* gw_w2  = (const float*)d_in[12];
    const float* gw_b2  = (const float*)d_in[13];
    const float* ew_w   = (const float*)d_in[14];
    const float* ew_b   = (const float*)d_in[15];
    const int*   eidx   = (const int*)d_in[16];
    const int*   deg    = (const int*)d_in[17];
    const int*   batch  = (const int*)d_in[18];
    const int*   heads  = (const int*)d_in[19];
    const int*   tails  = (const int*)d_in[20];
    const int* src  = eidx;
    const int* recv = eidx + E_TOT;
    float* out = (float*)d_out;
    const float* w1a = eu_w1;
    const float* w1b = eu_w1 + 258 * H;
    const float* w1c = eu_w1 + 516 * H;

    cudaFuncSetAttribute(edge_gemm<0>, cudaFuncAttributeMaxDynamicSharedMemorySize, S_SMEM);
    cudaFuncSetAttribute(edge_gemm<1>, cudaFuncAttributeMaxDynamicSharedMemorySize, S_SMEM);
    cudaFuncSetAttribute(node_gemm, cudaFuncAttributeMaxDynamicSharedMemorySize, N_SMEM);

    float *p_cbsc = dev_ptr(g_cbsc), *p_cbth = dev_ptr(g_cbth);
    float *p_cU = dev_ptr(g_cU), *p_cV = dev_ptr(g_cV);
    float *p_agg = dev_ptr(g_agg);
    __half *p_hidden = (__half*)dev_ptr(g_hidden);
    __half *h_sc0 = (__half*)dev_ptr(g_h_sc0), *h_sc = (__half*)dev_ptr(g_h_sc);
    __half *h_th0 = (__half*)dev_ptr(g_h_th0), *h_th = (__half*)dev_ptr(g_h_th);
    __half *h_u = (__half*)dev_ptr(g_h_u), *h_v = (__half*)dev_ptr(g_h_v);
    __half *h_u2 = (__half*)dev_ptr(g_h_u2), *h_v2 = (__half*)dev_ptr(g_h_v2);
    __half *h_w2 = (__half*)dev_ptr(g_h_w2);

    // ---- prep (4 launches) ----
    deg_kernel<<<NN / 256, 256>>>(deg, batch, heads, tails);
    CompJobs cj;
    cj.R[0] = ea_w1; cj.dst[0] = h_sc;
    cj.R[1] = w1c;   cj.dst[1] = h_th;
    cj.R[2] = w1a;   cj.dst[2] = h_u2;
    cj.R[3] = w1b;   cj.dst[3] = h_v2;
    comp_mat_h<<<dim3(256, 4), 256>>>(eu_w2, cj);
    comp_vec<<<256, 256>>>(eu_w2, eu_b2, ea_w1, ea_b1, w1c, eu_b1, w1a, w1b, ew_w, ew_b);
    ConvJobs vj;
    vj.src[0] = ea_w1; vj.dst[0] = h_sc0;
    vj.src[1] = w1c;   vj.dst[1] = h_th0;
    vj.src[2] = w1a;   vj.dst[2] = h_u;
    vj.src[3] = w1b;   vj.dst[3] = h_v;
    vj.src[4] = eu_w2; vj.dst[4] = h_w2;
    conv_w_batch<<<dim3(256, 5), 256>>>(vj);

    for (int it = 0; it < 3; it++) {
        init_iter_kernel<<<(NN * H + 255) / 256, 256>>>(p_agg);
        if (it == 0)
            edge_gemm<1><<<8192, 256, S_SMEM>>>(
                ef, gall, nullptr, h_sc0, h_th0, ea_b1, eu_b1,
                ea_w2, ea_b2, recv, p_agg);
        else
            edge_gemm<0><<<8192, 256, S_SMEM>>>(
                nullptr, nullptr, p_hidden, h_sc, h_th, p_cbsc, p_cbth,
                ea_w2, ea_b2, recv, p_agg);
        node_gemm<<<(it == 2) ? 768 : 512, 256, N_SMEM>>>(
            (it == 0) ? h_u : h_u2, (it == 0) ? h_v : h_v2, h_w2,
            (it == 0) ? nullptr : p_cU, (it == 0) ? nullptr : p_cV, eu_b2,
            eu_w1 + 256 * H, eu_w1 + 257 * H, eu_w1 + 514 * H, eu_w1 + 515 * H);
        if (it < 2)
            finalize_hidden<<<E_TOT / 8, 256>>>(src, recv);
        else
            finalize_we<<<E_TOT / 8, 256>>>(src, recv, out);
    }

    gmax_kernel<<<NG, 256>>>(heads, tails);
    gmlp_kernel<<<NG, 256>>>(gw_w1, gw_b1, gw_w2, gw_b2);
    gout_kernel<<<1, 768>>>(out + E_TOT);
}

// round 17
// speedup vs baseline: 1.0303x; 1.0303x over previous
#include <cuda_runtime.h>
#include <cuda_fp16.h>
#include <cstdint>
#include <math.h>

#define E_TOT 262144
#define NN    16384
#define H     256
#define NG    64

// ---------------- scratch ----------------
__device__ __half g_hidden[(size_t)E_TOT * H];  // hidden_t, fp16
__device__ __half g_pre[(size_t)E_TOT * H];     // hidden pre-activation, fp16
__device__ float g_s[NN];
__device__ float g_bv[(size_t)NN * H];
__device__ float g_agg[(size_t)NN * H];
__device__ float g_U[(size_t)NN * H];
__device__ float g_V[(size_t)NN * H];
__device__ float g_gG[NG * 768];
__device__ float g_z[NG];

// composed fp32 vectors
__device__ float g_cbsc[H];
__device__ float g_cbth[H];
__device__ float g_cU[H];
__device__ float g_cV[H];
__device__ float g_wcomp[H];
__device__ float g_cconst[1];
__device__ float g_inv[NN], g_rs[NN], g_ish[NN], g_ist[NN];

// fp16 weights, K-major B[n][k]
__device__ __half g_h_sc0[H*H];
__device__ __half g_h_sc[H*H];
__device__ __half g_h_th0[H*H];
__device__ __half g_h_th[H*H];
__device__ __half g_h_u[H*H];
__device__ __half g_h_v[H*H];
__device__ __half g_h_u2[H*H];
__device__ __half g_h_v2[H*H];
__device__ __half g_h_w2[H*H];

// ---------------- prep kernels ----------------

struct CompJobs { const float* R[4]; __half* dst[4]; };
__global__ void comp_mat_h(const float* __restrict__ L, CompJobs jobs) {
    __shared__ float lrow[H];
    int m = blockIdx.y, k = blockIdx.x, n = threadIdx.x;
    lrow[n] = L[k * H + n];
    __syncthreads();
    const float* R = jobs.R[m];
    float acc = 0.f;
    for (int j = 0; j < H; j++) acc = fmaf(lrow[j], R[j * H + n], acc);
    jobs.dst[m][(size_t)n * H + k] = __float2half_rn(acc);
}

struct ConvJobs { const float* src[5]; __half* dst[5]; };
__global__ void conv_w_batch(ConvJobs jobs) {
    int m = blockIdx.y;
    int idx = blockIdx.x * 256 + threadIdx.x;
    int n = idx >> 8, k = idx & 255;
    jobs.dst[m][(size_t)n * H + k] = __float2half_rn(jobs.src[m][(size_t)k * H + n]);
}

// grid (256 + NN/256): first 256 blocks do composed vectors, rest do degree tables
__global__ void comp_vec(const float* __restrict__ eu_w2, const float* __restrict__ eu_b2,
                         const float* __restrict__ ea_w1, const float* __restrict__ ea_b1,
                         const float* __restrict__ w1c, const float* __restrict__ eu_b1,
                         const float* __restrict__ w1a, const float* __restrict__ w1b,
                         const float* __restrict__ ew_w, const float* __restrict__ ew_b,
                         const int* __restrict__ deg, const int* __restrict__ batch,
                         const int* __restrict__ heads, const int* __restrict__ tails) {
    if (blockIdx.x >= 256) {
        int n = (blockIdx.x - 256) * 256 + threadIdx.x;
        int d = deg[n];
        float inv = 1.f / (1.f + (float)d);
        g_inv[n] = inv;
        g_rs[n] = (d > 0) ? inv : 0.f;
        int b = batch[n];
        g_ish[n] = (heads[b] == n) ? 1.f : 0.f;
        g_ist[n] = (tails[b] == n) ? 1.f : 0.f;
        return;
    }
    __shared__ float ra[H], rb[H], rw[H], rc[H], ru[H], rv[H];
    int n = blockIdx.x, k = threadIdx.x;
    float e2 = eu_b2[k];
    ra[k] = e2 * ea_w1[k * H + n];
    rb[k] = e2 * w1c[k * H + n];
    ru[k] = e2 * w1a[k * H + n];
    rv[k] = e2 * w1b[k * H + n];
    rw[k] = eu_w2[n * H + k] * ew_w[k];
    rc[k] = e2 * ew_w[k];
    __syncthreads();
    for (int s = 128; s > 0; s >>= 1) {
        if (k < s) {
            ra[k] += ra[k+s]; rb[k] += rb[k+s]; rw[k] += rw[k+s];
            rc[k] += rc[k+s]; ru[k] += ru[k+s]; rv[k] += rv[k+s];
        }
        __syncthreads();
    }
    if (k == 0) {
        g_cbsc[n] = ra[0] + ea_b1[n];
        g_cbth[n] = rb[0] + eu_b1[n];
        g_cU[n] = ru[0];
        g_cV[n] = rv[0];
        g_wcomp[n] = rw[0];
        if (n == 0) g_cconst[0] = rc[0] + ew_b[0];
    }
}

__global__ void init_iter_kernel() {
    int t = blockIdx.x * 256 + threadIdx.x;      // NN*H/4 threads
    *(float4*)(g_agg + (size_t)t * 4) = make_float4(0.f, 0.f, 0.f, 0.f);
    if (t < NN) g_s[t] = 0.f;
}

// ---------------- common helpers ----------------

#define MMA_F16(d, a, b0, b1)                                               \
    asm volatile("mma.sync.aligned.m16n8k16.row.col.f32.f16.f16.f32 "       \
        "{%0,%1,%2,%3}, {%4,%5,%6,%7}, {%8,%9}, {%0,%1,%2,%3};"             \
        : "+f"((d)[0]), "+f"((d)[1]), "+f"((d)[2]), "+f"((d)[3])            \
        : "r"((a)[0]), "r"((a)[1]), "r"((a)[2]), "r"((a)[3]),               \
          "r"(b0), "r"(b1))

#define LDSM_X4(r, addr)                                                    \
    asm volatile("ldmatrix.sync.aligned.m8n8.x4.shared.b16 {%0,%1,%2,%3}, [%4];" \
        : "=r"((r)[0]), "=r"((r)[1]), "=r"((r)[2]), "=r"((r)[3]) : "r"(addr))

__device__ __forceinline__ uint32_t pack_h2(float x, float y) {
    __half2 h = __floats2half2_rn(x, y);
    return *(uint32_t*)&h;
}

__device__ __forceinline__ uint32_t smem_u32(const void* p) {
    return (uint32_t)__cvta_generic_to_shared(p);
}

// ---------------- fused edge GEMM: score(+softmax+scatter) | hidden-pre ----------------
// (R14 configuration: single-buffer B + register prefetch + LDSM)

#define AFSTRIDE 264
#define S_OFF_A    0                    // 64*264*2 = 33792
#define S_OFF_B    33792                // 256*40*2 = 20480
#define S_OFF_SB1  54272
#define S_OFF_SWV  55296
#define S_OFF_RSUM 56320
#define S_OFF_SEX  56576
#define S_OFF_RCV  56832
#define S_SMEM     57088
#define BSTRIDE 40
#define ASTRIDE 40

template<int FIRST>
__global__ __launch_bounds__(256, 2) void edge_gemm(
    const float* __restrict__ ef, const float* __restrict__ gall,
    const __half* __restrict__ Ahid,
    const __half* __restrict__ Bsc, const __half* __restrict__ Bth,
    const float* __restrict__ bsc, const float* __restrict__ bth,
    const float* __restrict__ wvp, const float* __restrict__ wbp,
    const int* __restrict__ recvp, float* __restrict__ aggdst)
{
    extern __shared__ char smem[];
    __half* Af = (__half*)(smem + S_OFF_A);
    __half* Bh = (__half*)(smem + S_OFF_B);
    float* sb1  = (float*)(smem + S_OFF_SB1);
    float* swv  = (float*)(smem + S_OFF_SWV);
    float* rsum = (float*)(smem + S_OFF_RSUM);
    float* sex  = (float*)(smem + S_OFF_SEX);
    int*   srcv = (int*)(smem + S_OFF_RCV);

    const int tid = threadIdx.x, lane = tid & 31, wid = tid >> 5;
    const int half = blockIdx.x >> 12;          // 0 = score, 1 = pre
    const int row0 = (blockIdx.x & 4095) * 64;
    const int mbase = (wid >> 2) * 32, nbase = (wid & 3) * 64;
    const __half* Bg = half ? Bth : Bsc;

    sb1[tid] = half ? bth[tid] : bsc[tid];
    if (!half) {
        swv[tid] = wvp[tid];
        if (tid < 64) { rsum[tid] = 0.f; srcv[tid] = recvp[row0 + tid]; }
    }

    // ---- build/load A tile (64 x 256 halves) ----
    {
        int r = tid >> 2, c0 = (tid & 3) * 64;
        if (FIRST) {
            #pragma unroll
            for (int j = 0; j < 8; j++) {
                int c = c0 + j * 8;
                const float* sp = (c < 192) ? (ef + (size_t)(row0 + r) * 192 + c)
                                            : (gall + (c - 192));
                float4 a = *(const float4*)sp;
                float4 b = *(const float4*)(sp + 4);
                uint4 u;
                u.x = pack_h2(a.x, a.y); u.y = pack_h2(a.z, a.w);
                u.z = pack_h2(b.x, b.y); u.w = pack_h2(b.z, b.w);
                *(uint4*)&Af[r * AFSTRIDE + c] = u;
            }
        } else {
            #pragma unroll
            for (int j = 0; j < 8; j++) {
                uint4 u = *(const uint4*)(Ahid + (size_t)(row0 + r) * H + c0 + j * 8);
                *(uint4*)&Af[r * AFSTRIDE + c0 + j * 8] = u;
            }
        }
    }

    float acc[2][8][4];
    #pragma unroll
    for (int mf = 0; mf < 2; mf++)
        #pragma unroll
        for (int nf = 0; nf < 8; nf++)
            #pragma unroll
            for (int q = 0; q < 4; q++) acc[mf][nf][q] = 0.f;

    // per-lane LDSM base addresses
    const uint32_t a_base = smem_u32(Af)
        + (uint32_t)(((mbase + (lane & 15)) * AFSTRIDE + ((lane >> 4) * 8)) * 2);
    const uint32_t b_base = smem_u32(Bh)
        + (uint32_t)((((nbase + ((lane >> 4) * 8) + (lane & 7)) * BSTRIDE)
                      + (((lane >> 3) & 1) * 8)) * 2);

    // B prefetch pipeline
    const __half* bptr = Bg + (size_t)tid * H;
    uint4 bf[4];
    #pragma unroll
    for (int j = 0; j < 4; j++) bf[j] = *(const uint4*)(bptr + j * 8);

    for (int kt = 0; kt < H; kt += 32) {
        #pragma unroll
        for (int j = 0; j < 4; j++) *(uint4*)&Bh[tid * BSTRIDE + j * 8] = bf[j];
        __syncthreads();
        if (kt + 32 < H) {
            #pragma unroll
            for (int j = 0; j < 4; j++) bf[j] = *(const uint4*)(bptr + kt + 32 + j * 8);
        }
        #pragma unroll
        for (int ks = 0; ks < 2; ks++) {
            uint32_t af0[4], af1[4];
            LDSM_X4(af0, a_base + (uint32_t)((kt + ks * 16) * 2));
            LDSM_X4(af1, a_base + (uint32_t)((kt + ks * 16) * 2 + 16 * AFSTRIDE * 2));
            #pragma unroll
            for (int p = 0; p < 4; p++) {
                uint32_t bb[4];
                LDSM_X4(bb, b_base + (uint32_t)((p * 16 * BSTRIDE + ks * 16) * 2));
                MMA_F16(acc[0][2 * p],     af0, bb[0], bb[1]);
                MMA_F16(acc[1][2 * p],     af1, bb[0], bb[1]);
                MMA_F16(acc[0][2 * p + 1], af0, bb[2], bb[3]);
                MMA_F16(acc[1][2 * p + 1], af1, bb[2], bb[3]);
            }
        }
        __syncthreads();
    }

    if (half) {
        #pragma unroll
        for (int mf = 0; mf < 2; mf++)
            #pragma unroll
            for (int nf = 0; nf < 8; nf++) {
                int rA = mbase + mf * 16 + (lane >> 2);
                int rB = rA + 8;
                int c0 = nbase + nf * 8 + (lane & 3) * 2;
                float bb0 = sb1[c0], bb1 = sb1[c0 + 1];
                *(uint32_t*)(g_pre + (size_t)(row0 + rA) * H + c0) =
                    pack_h2(acc[mf][nf][0] + bb0, acc[mf][nf][1] + bb1);
                *(uint32_t*)(g_pre + (size_t)(row0 + rB) * H + c0) =
                    pack_h2(acc[mf][nf][2] + bb0, acc[mf][nf][3] + bb1);
            }
    } else {
        float part[2][2] = {{0.f, 0.f}, {0.f, 0.f}};
        #pragma unroll
        for (int mf = 0; mf < 2; mf++)
            #pragma unroll
            for (int nf = 0; nf < 8; nf++) {
                int c0 = nbase + nf * 8 + (lane & 3) * 2;
                float w0 = swv[c0], w1 = swv[c0 + 1];
                float bb0 = sb1[c0], bb1 = sb1[c0 + 1];
                float v0 = fmaxf(acc[mf][nf][0] + bb0, 0.f);
                float v1 = fmaxf(acc[mf][nf][1] + bb1, 0.f);
                float v2 = fmaxf(acc[mf][nf][2] + bb0, 0.f);
                float v3 = fmaxf(acc[mf][nf][3] + bb1, 0.f);
                part[mf][0] = fmaf(v0, w0, fmaf(v1, w1, part[mf][0]));
                part[mf][1] = fmaf(v2, w0, fmaf(v3, w1, part[mf][1]));
            }
        #pragma unroll
        for (int off = 1; off <= 2; off <<= 1)
            #pragma unroll
            for (int mf = 0; mf < 2; mf++) {
                part[mf][0] += __shfl_xor_sync(0xffffffffu, part[mf][0], off);
                part[mf][1] += __shfl_xor_sync(0xffffffffu, part[mf][1], off);
            }
        if ((lane & 3) == 0) {
            #pragma unroll
            for (int mf = 0; mf < 2; mf++) {
                atomicAdd(&rsum[mbase + mf * 16 + (lane >> 2)],     part[mf][0]);
                atomicAdd(&rsum[mbase + mf * 16 + (lane >> 2) + 8], part[mf][1]);
            }
        }
        __syncthreads();
        if (tid < 64) {
            float sg = 1.f / (1.f + expf(-(rsum[tid] + wbp[0])));
            float ex = expf(sg);
            sex[tid] = ex;
            atomicAdd(&g_s[srcv[tid]], ex);
        }
        __syncthreads();
        int r = tid >> 2, c0 = (tid & 3) * 64;
        float exv = sex[r];
        float* drow = aggdst + (size_t)srcv[r] * H + c0;
        const __half* arow = Af + r * AFSTRIDE + c0;
        #pragma unroll
        for (int j = 0; j < 16; j++) {
            float2 f0 = __half22float2(*(const __half2*)(arow + j * 4));
            float2 f1 = __half22float2(*(const __half2*)(arow + j * 4 + 2));
            asm volatile("red.global.add.v4.f32 [%0], {%1, %2, %3, %4};"
                         :: "l"(drow + j * 4), "f"(exv * f0.x), "f"(exv * f0.y),
                            "f"(exv * f1.x), "f"(exv * f1.y) : "memory");
        }
    }
}

// ---------------- node GEMM: roles U | V | bv from row-scaled agg ----------------

#define N_OFF_AH 0
#define N_OFF_BH 5120
#define N_OFF_CV 25600
#define N_OFF_FH 26624
#define N_OFF_FT 27648
#define N_OFF_R1 28672
#define N_OFF_R2 28928
#define N_OFF_I1 29184
#define N_OFF_I2 29440
#define N_SMEM   29696

__global__ __launch_bounds__(256) void node_gemm(
    const __half* __restrict__ Bu, const __half* __restrict__ Bv,
    const __half* __restrict__ Bw2,
    const float* __restrict__ cU, const float* __restrict__ cV,
    const float* __restrict__ cBv,
    const float* __restrict__ fhU, const float* __restrict__ ftU,
    const float* __restrict__ fhV, const float* __restrict__ ftV)
{
    extern __shared__ char smem[];
    __half* Ah = (__half*)(smem + N_OFF_AH);
    __half* Bh = (__half*)(smem + N_OFF_BH);
    float* scv = (float*)(smem + N_OFF_CV);
    float* sfh = (float*)(smem + N_OFF_FH);
    float* sft = (float*)(smem + N_OFF_FT);
    float* s_r1 = (float*)(smem + N_OFF_R1);
    float* s_r2 = (float*)(smem + N_OFF_R2);
    float* s_i1 = (float*)(smem + N_OFF_I1);
    float* s_i2 = (float*)(smem + N_OFF_I2);

    const int tid = threadIdx.x, lane = tid & 31, wid = tid >> 5;
    const int role = blockIdx.x >> 8;
    const int row0 = (blockIdx.x & 255) * 64;
    const int mbase = (wid >> 2) * 32, nbase = (wid & 3) * 64;

    const __half* Bg = (role == 0) ? Bu : (role == 1) ? Bv : Bw2;
    const float* cvec = (role == 0) ? cU : (role == 1) ? cV : cBv;
    const float* fh = (role == 0) ? fhU : (role == 1) ? fhV : nullptr;
    const float* ft = (role == 0) ? ftU : (role == 1) ? ftV : nullptr;
    float* outp = (role == 0) ? g_U : (role == 1) ? g_V : g_bv;

    scv[tid] = cvec ? cvec[tid] : 0.f;
    sfh[tid] = fh ? fh[tid] : 0.f;
    sft[tid] = ft ? ft[tid] : 0.f;
    if (tid < 64) {
        int n = row0 + tid;
        float s = g_s[n];
        s_r1[tid] = (s > 0.f) ? g_inv[n] / s : 0.f;
        s_r2[tid] = g_rs[n];
        s_i1[tid] = g_ish[n];
        s_i2[tid] = g_ist[n];
    }
    __syncthreads();

    float acc[2][8][4];
    #pragma unroll
    for (int mf = 0; mf < 2; mf++)
        #pragma unroll
        for (int nf = 0; nf < 8; nf++)
            #pragma unroll
            for (int q = 0; q < 4; q++) acc[mf][nf][q] = 0.f;

    const int arow = tid >> 2, ac0 = (tid & 3) * 8;

    for (int kt = 0; kt < H; kt += 32) {
        {
            float x[8];
            *(float4*)&x[0] = *(const float4*)(g_agg + (size_t)(row0 + arow) * H + kt + ac0);
            *(float4*)&x[4] = *(const float4*)(g_agg + (size_t)(row0 + arow) * H + kt + ac0 + 4);
            float sc = s_r1[arow];
            uint4 u;
            u.x = pack_h2(x[0] * sc, x[1] * sc);
            u.y = pack_h2(x[2] * sc, x[3] * sc);
            u.z = pack_h2(x[4] * sc, x[5] * sc);
            u.w = pack_h2(x[6] * sc, x[7] * sc);
            *(uint4*)&Ah[arow * ASTRIDE + ac0] = u;
        }
        {
            const __half* bsrc = Bg + (size_t)tid * H + kt;
            #pragma unroll
            for (int j = 0; j < 4; j++)
                *(uint4*)&Bh[tid * BSTRIDE + j * 8] = *(const uint4*)(bsrc + j * 8);
        }
        __syncthreads();
        #pragma unroll
        for (int ks = 0; ks < 2; ks++) {
            const int k0 = ks * 16 + (lane & 3) * 2;
            uint32_t af[2][4];
            #pragma unroll
            for (int mf = 0; mf < 2; mf++) {
                int r = mbase + mf * 16 + (lane >> 2);
                af[mf][0] = *(uint32_t*)&Ah[r * ASTRIDE + k0];
                af[mf][1] = *(uint32_t*)&Ah[(r + 8) * ASTRIDE + k0];
                af[mf][2] = *(uint32_t*)&Ah[r * ASTRIDE + k0 + 8];
                af[mf][3] = *(uint32_t*)&Ah[(r + 8) * ASTRIDE + k0 + 8];
            }
            #pragma unroll
            for (int nf = 0; nf < 8; nf++) {
                int n = nbase + nf * 8 + (lane >> 2);
                uint32_t b0 = *(uint32_t*)&Bh[n * BSTRIDE + k0];
                uint32_t b1 = *(uint32_t*)&Bh[n * BSTRIDE + k0 + 8];
                #pragma unroll
                for (int mf = 0; mf < 2; mf++)
                    MMA_F16(acc[mf][nf], af[mf], b0, b1);
            }
        }
        __syncthreads();
    }

    #pragma unroll
    for (int mf = 0; mf < 2; mf++)
        #pragma unroll
        for (int nf = 0; nf < 8; nf++) {
            int rA = mbase + mf * 16 + (lane >> 2);
            int rB = rA + 8;
            int c0 = nbase + nf * 8 + (lane & 3) * 2;
            float cv0 = scv[c0], cv1 = scv[c0 + 1];
            float fh0 = sfh[c0], fh1 = sfh[c0 + 1];
            float ft0 = sft[c0], ft1 = sft[c0 + 1];
            float2 v0, v1;
            v0.x = acc[mf][nf][0] + s_r2[rA] * cv0 + s_i1[rA] * fh0 + s_i2[rA] * ft0;
            v0.y = acc[mf][nf][1] + s_r2[rA] * cv1 + s_i1[rA] * fh1 + s_i2[rA] * ft1;
            v1.x = acc[mf][nf][2] + s_r2[rB] * cv0 + s_i1[rB] * fh0 + s_i2[rB] * ft0;
            v1.y = acc[mf][nf][3] + s_r2[rB] * cv1 + s_i1[rB] * fh1 + s_i2[rB] * ft1;
            *(float2*)(outp + (size_t)(row0 + rA) * H + c0) = v0;
            *(float2*)(outp + (size_t)(row0 + rB) * H + c0) = v1;
        }
}

// ---------------- finalize: hidden = relu(pre + U[src] + V[recv]) ----------------

__global__ void finalize_hidden(const int* __restrict__ srcp, const int* __restrict__ recvp) {
    int t = blockIdx.x * 256 + threadIdx.x;
    int e = t >> 5, j = (t & 31) * 8;
    int s = srcp[e], r = recvp[e];
    uint4 ph = *(const uint4*)(g_pre + (size_t)e * H + j);
    float4 u0 = *(const float4*)(g_U + (size_t)s * H + j);
    float4 u1 = *(const float4*)(g_U + (size_t)s * H + j + 4);
    float4 v0 = *(const float4*)(g_V + (size_t)r * H + j);
    float4 v1 = *(const float4*)(g_V + (size_t)r * H + j + 4);
    float2 p0 = __half22float2(*(__half2*)&ph.x);
    float2 p1 = __half22float2(*(__half2*)&ph.y);
    float2 p2 = __half22float2(*(__half2*)&ph.z);
    float2 p3 = __half22float2(*(__half2*)&ph.w);
    uint4 o;
    o.x = pack_h2(fmaxf(p0.x + u0.x + v0.x, 0.f), fmaxf(p0.y + u0.y + v0.y, 0.f));
    o.y = pack_h2(fmaxf(p1.x + u0.z + v0.z, 0.f), fmaxf(p1.y + u0.w + v0.w, 0.f));
    o.z = pack_h2(fmaxf(p2.x + u1.x + v1.x, 0.f), fmaxf(p2.y + u1.y + v1.y, 0.f));
    o.w = pack_h2(fmaxf(p3.x + u1.z + v1.z, 0.f), fmaxf(p3.y + u1.w + v1.w, 0.f));
    *(uint4*)(g_hidden + (size_t)e * H + j) = o;
}

__global__ void finalize_we(const int* __restrict__ srcp, const int* __restrict__ recvp,
                            float* __restrict__ out) {
    __shared__ float wc[H];
    int tid = threadIdx.x, lane = tid & 31, wid = tid >> 5;
    wc[tid] = g_wcomp[tid];
    __syncthreads();
    int e = blockIdx.x * 8 + wid;
    int s = srcp[e], r = recvp[e];
    int j = lane * 8;
    uint4 ph = *(const uint4*)(g_pre + (size_t)e * H + j);
    float4 u0 = *(const float4*)(g_U + (size_t)s * H + j);
    float4 u1 = *(const float4*)(g_U + (size_t)s * H + j + 4);
    float4 v0 = *(const float4*)(g_V + (size_t)r * H + j);
    float4 v1 = *(const float4*)(g_V + (size_t)r * H + j + 4);
    float2 p0 = __half22float2(*(__half2*)&ph.x);
    float2 p1 = __half22float2(*(__half2*)&ph.y);
    float2 p2 = __half22float2(*(__half2*)&ph.z);
    float2 p3 = __half22float2(*(__half2*)&ph.w);
    const float* w = wc + j;
    float acc = fmaxf(p0.x + u0.x + v0.x, 0.f) * w[0]
              + fmaxf(p0.y + u0.y + v0.y, 0.f) * w[1]
              + fmaxf(p1.x + u0.z + v0.z, 0.f) * w[2]
              + fmaxf(p1.y + u0.w + v0.w, 0.f) * w[3]
              + fmaxf(p2.x + u1.x + v1.x, 0.f) * w[4]
              + fmaxf(p2.y + u1.y + v1.y, 0.f) * w[5]
              + fmaxf(p3.x + u1.z + v1.z, 0.f) * w[6]
              + fmaxf(p3.y + u1.w + v1.w, 0.f) * w[7];
    #pragma unroll
    for (int off = 16; off > 0; off >>= 1) acc += __shfl_xor_sync(0xffffffffu, acc, off);
    if (lane == 0) out[e] = 1.f / (1.f + expf(-(acc + g_cconst[0])));
}

// ---------------- graph readout ----------------

__global__ void gmax_kernel(const int* __restrict__ heads, const int* __restrict__ tails) {
    int g = blockIdx.x, j = threadIdx.x;
    float mx = -3.4e38f;
    int base = g * 256;
    for (int n = 0; n < 256; n++)
        mx = fmaxf(mx, g_bv[(size_t)(base + n) * H + j]);
    g_gG[g * 768 + j]       = mx;
    g_gG[g * 768 + 256 + j] = g_bv[(size_t)heads[g] * H + j];
    g_gG[g * 768 + 512 + j] = g_bv[(size_t)tails[g] * H + j];
}

__global__ void gmlp_kernel(const float* __restrict__ W1, const float* __restrict__ b1,
                            const float* __restrict__ w2, const float* __restrict__ b2) {
    __shared__ float row[768];
    __shared__ float red[256];
    int g = blockIdx.x, tid = threadIdx.x;
    for (int i = tid; i < 768; i += 256) row[i] = g_gG[g * 768 + i];
    __syncthreads();
    float h = b1[tid];
    for (int k = 0; k < 768; k++) h = fmaf(row[k], W1[(size_t)k * 256 + tid], h);
    h = fmaxf(h, 0.f);
    red[tid] = h * w2[tid];
    __syncthreads();
    for (int s = 128; s > 0; s >>= 1) {
        if (tid < s) red[tid] += red[tid + s];
        __syncthreads();
    }
    if (tid == 0) g_z[g] = red[0] + b2[0];
}

__global__ void gout_kernel(float* __restrict__ out) {
    __shared__ float zs[NG];
    int tid = threadIdx.x;
    if (tid < NG) zs[tid] = g_z[tid];
    __syncthreads();
    float m = -3.4e38f;
    for (int g = 0; g < NG; g++) m = fmaxf(m, zs[g]);
    float denom = 0.f;
    for (int g = 0; g < NG; g++) denom += expf(zs[g] - m);
    float acc = 0.f;
    for (int g = 0; g < NG; g++) acc += (expf(zs[g] - m) / denom) * g_gG[g * 768 + tid];
    out[tid] = acc;
}

// ---------------- launch ----------------

static float* dev_ptr(const void* sym) { void* p = nullptr; cudaGetSymbolAddress(&p, sym); return (float*)p; }

extern "C" void kernel_launch(void* const* d_in, const int* in_sizes, int n_in,
                              void* d_out, int out_size) {
    const float* ef     = (const float*)d_in[0];
    const float* gall   = (const float*)d_in[1];
    const float* ea_w1  = (const float*)d_in[2];
    const float* ea_b1  = (const float*)d_in[3];
    const float* ea_w2  = (const float*)d_in[4];
    const float* ea_b2  = (const float*)d_in[5];
    const float* eu_w1  = (const float*)d_in[6];
    const float* eu_b1  = (const float*)d_in[7];
    const float* eu_w2  = (const float*)d_in[8];
    const float* eu_b2  = (const float*)d_in[9];
    const float* gw_w1  = (const float*)d_in[10];
    const float* gw_b1  = (const float*)d_in[11];
    const float* gw_w2  = (const float*)d_in[12];
    const float* gw_b2  = (const float*)d_in[13];
    const float* ew_w   = (const float*)d_in[14];
    const float* ew_b   = (const float*)d_in[15];
    const int*   eidx   = (const int*)d_in[16];
    const int*   deg    = (const int*)d_in[17];
    const int*   batch  = (const int*)d_in[18];
    const int*   heads  = (const int*)d_in[19];
    const int*   tails  = (const int*)d_in[20];
    const int* src  = eidx;
    const int* recv = eidx + E_TOT;
    float* out = (float*)d_out;
    const float* w1a = eu_w1;
    const float* w1b = eu_w1 + 258 * H;
    const float* w1c = eu_w1 + 516 * H;

    cudaFuncSetAttribute(edge_gemm<0>, cudaFuncAttributeMaxDynamicSharedMemorySize, S_SMEM);
    cudaFuncSetAttribute(edge_gemm<1>, cudaFuncAttributeMaxDynamicSharedMemorySize, S_SMEM);
    cudaFuncSetAttribute(node_gemm, cudaFuncAttributeMaxDynamicSharedMemorySize, N_SMEM);

    float *p_cbsc = dev_ptr(g_cbsc), *p_cbth = dev_ptr(g_cbth);
    float *p_cU = dev_ptr(g_cU), *p_cV = dev_ptr(g_cV);
    float *p_agg = dev_ptr(g_agg);
    __half *p_hidden = (__half*)dev_ptr(g_hidden);
    __half *h_sc0 = (__half*)dev_ptr(g_h_sc0), *h_sc = (__half*)dev_ptr(g_h_sc);
    __half *h_th0 = (__half*)dev_ptr(g_h_th0), *h_th = (__half*)dev_ptr(g_h_th);
    __half *h_u = (__half*)dev_ptr(g_h_u), *h_v = (__half*)dev_ptr(g_h_v);
    __half *h_u2 = (__half*)dev_ptr(g_h_u2), *h_v2 = (__half*)dev_ptr(g_h_v2);
    __half *h_w2 = (__half*)dev_ptr(g_h_w2);

    // ---- prep (3 launches) ----
    CompJobs cj;
    cj.R[0] = ea_w1; cj.dst[0] = h_sc;
    cj.R[1] = w1c;   cj.dst[1] = h_th;
    cj.R[2] = w1a;   cj.dst[2] = h_u2;
    cj.R[3] = w1b;   cj.dst[3] = h_v2;
    comp_mat_h<<<dim3(256, 4), 256>>>(eu_w2, cj);
    comp_vec<<<256 + NN / 256, 256>>>(eu_w2, eu_b2, ea_w1, ea_b1, w1c, eu_b1,
                                      w1a, w1b, ew_w, ew_b, deg, batch, heads, tails);
    ConvJobs vj;
    vj.src[0] = ea_w1; vj.dst[0] = h_sc0;
    vj.src[1] = w1c;   vj.dst[1] = h_th0;
    vj.src[2] = w1a;   vj.dst[2] = h_u;
    vj.src[3] = w1b;   vj.dst[3] = h_v;
    vj.src[4] = eu_w2; vj.dst[4] = h_w2;
    conv_w_batch<<<dim3(256, 5), 256>>>(vj);

    for (int it = 0; it < 3; it++) {
        init_iter_kernel<<<(NN * H / 4) / 256, 256>>>();
        if (it == 0)
            edge_gemm<1><<<8192, 256, S_SMEM>>>(
                ef, gall, nullptr, h_sc0, h_th0, ea_b1, eu_b1,
                ea_w2, ea_b2, recv, p_agg);
        else
            edge_gemm<0><<<8192, 256, S_SMEM>>>(
                nullptr, nullptr, p_hidden, h_sc, h_th, p_cbsc, p_cbth,
                ea_w2, ea_b2, recv, p_agg);
        node_gemm<<<(it == 2) ? 768 : 512, 256, N_SMEM>>>(
            (it == 0) ? h_u : h_u2, (it == 0) ? h_v : h_v2, h_w2,
            (it == 0) ? nullptr : p_cU, (it == 0) ? nullptr : p_cV, eu_b2,
            eu_w1 + 256 * H, eu_w1 + 257 * H, eu_w1 + 514 * H, eu_w1 + 515 * H);
        if (it < 2)
            finalize_hidden<<<E_TOT / 8, 256>>>(src, recv);
        else
            finalize_we<<<E_TOT / 8, 256>>>(src, recv, out);
    }

    gmax_kernel<<<NG, 256>>>(heads, tails);
    gmlp_kernel<<<NG, 256>>>(gw_w1, gw_b1, gw_w2, gw_b2);
    gout_kernel<<<1, 768>>>(out + E_TOT);
}